// round 2
// baseline (speedup 1.0000x reference)
#include <cuda_runtime.h>
#include <cuda_bf16.h>

// Problem constants
#define Bn 64
#define Hn 1024
#define Sn 512
#define NT 256            // threads per CTA
#define EPT 4             // Hn / NT rows per thread
#define NW (NT / 32)      // 8 warps
#define TS 8              // steps per register tile
#define NTILE (Sn / TS)   // 64 tiles
#define EPSV 1e-8f

__device__ __forceinline__ float warp_sum(float v) {
#pragma unroll
    for (int off = 16; off > 0; off >>= 1)
        v += __shfl_xor_sync(0xffffffffu, v, off);
    return v;
}

__global__ __launch_bounds__(NT)
void orth_add_tsu_kernel(const float* __restrict__ tree,
                         const float* __restrict__ seq,
                         const float* __restrict__ mask,
                         float* __restrict__ out) {
    // Parity-double-buffered per-warp partials: (dot, hh, ss, pad)
    __shared__ float4 part[2][NW];

    const int b    = blockIdx.x;
    const int tid  = threadIdx.x;
    const int wid  = tid >> 5;
    const int lane = tid & 31;

    // Each thread owns rows r = tid + i*NT  (strided -> coalesced h I/O)
    float h[EPT];
    const float* rowp[EPT];
#pragma unroll
    for (int i = 0; i < EPT; i++) {
        const int r = tid + i * NT;
        h[i]    = tree[b * Hn + r];
        rowp[i] = seq + ((size_t)b * Hn + r) * Sn;
    }
    const float* mrow = mask + (size_t)b * Sn;

    // Double-buffered register tiles: TS=8 consecutive s per row (two float4s)
    float cur[EPT][TS], nxt[EPT][TS];
    float mcur[TS], mnxt[TS];

#pragma unroll
    for (int i = 0; i < EPT; i++) {
        *(float4*)&cur[i][0] = *(const float4*)(rowp[i] + 0);
        *(float4*)&cur[i][4] = *(const float4*)(rowp[i] + 4);
    }
    *(float4*)&mcur[0] = *(const float4*)(mrow + 0);
    *(float4*)&mcur[4] = *(const float4*)(mrow + 4);

    for (int tile = 0; tile < NTILE; tile++) {
        const int sn = (tile + 1) * TS;
        const bool more = (tile + 1) < NTILE;
        if (more) {
            // Prefetch next tile — independent of the scan chain, latency hidden.
#pragma unroll
            for (int i = 0; i < EPT; i++) {
                *(float4*)&nxt[i][0] = *(const float4*)(rowp[i] + sn);
                *(float4*)&nxt[i][4] = *(const float4*)(rowp[i] + sn + 4);
            }
            *(float4*)&mnxt[0] = *(const float4*)(mrow + sn);
            *(float4*)&mnxt[4] = *(const float4*)(mrow + sn + 4);
        }

#pragma unroll
        for (int j = 0; j < TS; j++) {
            const float m = mcur[j];
            // m is uniform across the whole CTA (depends only on (b, step)).
            // m == 0 -> update is identity: skip the entire step (reduction,
            // barrier, cos). Uniform branch, so __syncthreads stays legal.
            if (m == 0.0f) continue;

            float sv[EPT];
#pragma unroll
            for (int i = 0; i < EPT; i++) sv[i] = cur[i][j];

            // Per-thread partials over 4 rows
            float dot = 0.f, hh = 0.f, ss = 0.f;
#pragma unroll
            for (int i = 0; i < EPT; i++) {
                dot = fmaf(h[i], sv[i], dot);
                hh  = fmaf(h[i], h[i],  hh);
                ss  = fmaf(sv[i], sv[i], ss);
            }

            // Warp reduce: three interleaved 5-level butterflies
            dot = warp_sum(dot);
            hh  = warp_sum(hh);
            ss  = warp_sum(ss);

            const int p = j & 1;  // parity buffer — allows a single barrier/step
            if (lane == 0) part[p][wid] = make_float4(dot, hh, ss, 0.f);
            __syncthreads();

            // Every thread combines the 8 warp partials (redundant compute
            // beats a second barrier + broadcast).
            float d = 0.f, a = 0.f, q = 0.f;
#pragma unroll
            for (int w = 0; w < NW; w++) {
                const float4 v = part[p][w];
                d += v.x; a += v.y; q += v.z;
            }

            const float denom = fmaxf(sqrtf(a * q), EPSV);
            const float cosv  = __fdividef(d, denom);

            // h = clip(h + (s - h*cos) * m, -1, 1)   (m == 1 here)
#pragma unroll
            for (int i = 0; i < EPT; i++) {
                const float t = fmaf(-cosv, h[i], sv[i]);
                float hn = fmaf(m, t, h[i]);
                hn = fminf(fmaxf(hn, -1.f), 1.f);
                h[i] = hn;
            }
        }

        if (more) {
#pragma unroll
            for (int i = 0; i < EPT; i++)
#pragma unroll
                for (int j = 0; j < TS; j++) cur[i][j] = nxt[i][j];
#pragma unroll
            for (int j = 0; j < TS; j++) mcur[j] = mnxt[j];
        }
    }

    // Coalesced output write
#pragma unroll
    for (int i = 0; i < EPT; i++) {
        const int r = tid + i * NT;
        out[b * Hn + r] = h[i];
    }
}

extern "C" void kernel_launch(void* const* d_in, const int* in_sizes, int n_in,
                              void* d_out, int out_size) {
    const float* tree = (const float*)d_in[0];  // (B, H)
    const float* seq  = (const float*)d_in[1];  // (B, H, S)
    const float* mask = (const float*)d_in[2];  // (B, S)
    float* out = (float*)d_out;                 // (B, H)
    orth_add_tsu_kernel<<<Bn, NT>>>(tree, seq, mask, out);
}